// round 2
// baseline (speedup 1.0000x reference)
#include <cuda_runtime.h>
#include <cstdint>

#define FULLMASK 0xFFFFFFFFu

static constexpr int L = 64;
static constexpr int H = 32;
static constexpr int B = 1024;

__device__ __forceinline__ unsigned long long pack2(float lo, float hi) {
    unsigned long long r;
    asm("mov.b64 %0, {%1, %2};" : "=l"(r) : "f"(lo), "f"(hi));
    return r;
}
__device__ __forceinline__ void unpack2(unsigned long long v, float& lo, float& hi) {
    asm("mov.b64 {%0, %1}, %2;" : "=f"(lo), "=f"(hi) : "l"(v));
}
__device__ __forceinline__ unsigned long long ffma2(unsigned long long a,
                                                    unsigned long long b,
                                                    unsigned long long c) {
    unsigned long long d;
    asm("fma.rn.f32x2 %0, %1, %2, %3;" : "=l"(d) : "l"(a), "l"(b), "l"(c));
    return d;
}
__device__ __forceinline__ unsigned long long fadd2(unsigned long long a,
                                                    unsigned long long b) {
    unsigned long long d;
    asm("add.rn.f32x2 %0, %1, %2;" : "=l"(d) : "l"(a), "l"(b));
    return d;
}

__global__ void __launch_bounds__(32)
rnn2d_kernel(const int* __restrict__ x,        // [B, L, L] in {0,1}
             const float* __restrict__ Win,    // [4, H]
             const float* __restrict__ WcH,    // [H, H]
             const float* __restrict__ WcV,    // [H, H]
             const float* __restrict__ bV,     // [H]
             const float* __restrict__ Wout,   // [H, 2]
             const float* __restrict__ bout,   // [2]
             float* __restrict__ out)          // [B]
{
    // Per-warp (== per-CTA) scratch.
    // vbuf[c]: f32x2 partial pair of the NEXT row's vertical pre-activation at
    //          column c for this lane (WcV matvec + bias + one-hot input terms).
    __shared__ __align__(16) unsigned long long vbuf[L * H / 2 * 2]; // L*32 pairs? see below
    __shared__ __align__(16) float hslot[2][H];   // double-buffered h broadcast
    __shared__ int xrow[2][L];

    const int lane = threadIdx.x;
    const int sample = blockIdx.x;

    // ---- per-lane weights ----
    const float win0 = Win[0 * H + lane];
    const float win1 = Win[1 * H + lane];
    const float win2 = Win[2 * H + lane];
    const float win3 = Win[3 * H + lane];
    const float bv   = bV[lane];
    const float dwo  = Wout[lane * 2 + 0] - Wout[lane * 2 + 1];
    const float dbo  = bout[0] - bout[1];

    unsigned long long wch[16], wcv[16];
    #pragma unroll
    for (int k = 0; k < 16; k++) {
        wch[k] = pack2(WcH[(2 * k) * H + lane], WcH[(2 * k + 1) * H + lane]);
        wcv[k] = pack2(WcV[(2 * k) * H + lane], WcV[(2 * k + 1) * H + lane]);
    }

    const int* xs = x + (long)sample * (L * L);

    // Row 0 x + vbuf preamble (row 0 has cV = 0, stateV = 0: only bias + stateH).
    xrow[0][lane]      = xs[lane];
    xrow[0][lane + 32] = xs[lane + 32];
    __syncwarp();
    {
        int aprev = -1; // row 0 scans left->right; predecessor of c is c-1
        #pragma unroll 4
        for (int c2 = 0; c2 < L; c2++) {
            const float wa = (aprev == 0) ? win0 : ((aprev == 1) ? win1 : 0.f);
            vbuf[(c2 << 5) + lane] = pack2(bv + wa, 0.f);
            aprev = xrow[0][c2];
        }
    }

    unsigned long long hrep[16];   // replicated h of the just-finished column
    float logacc = 0.f;
    int hb = 0;                    // hslot buffer toggle

    for (int r = 0; r < L; r++) {
        const int cur = r & 1, nxt = cur ^ 1;
        const bool notlast = (r < L - 1);

        // Protect xrow[nxt] (buffer reuse across rows) against lagging lanes.
        __syncwarp();
        if (notlast) {
            xrow[nxt][lane]      = xs[(r + 1) * L + lane];
            xrow[nxt][lane + 32] = xs[(r + 1) * L + lane + 32];
        }
        const int dir = (r & 1) ? -1 : 1;
        int c = (r & 1) ? (L - 1) : 0;

        // ---- one column step ----
        auto stepbody = [&](int cc, bool firstcol) -> float {
            const unsigned long long vp = vbuf[(cc << 5) + lane];
            float pre;
            if (firstcol) {
                float lo, hi; unpack2(vp, lo, hi);
                pre = lo + hi;                       // hcarry = 0 at row start
            } else {
                unsigned long long a0 = vp, a1 = 0ull, a2 = 0ull, a3 = 0ull;
                #pragma unroll
                for (int k = 0; k < 16; k += 4) {
                    a0 = ffma2(hrep[k + 0], wch[k + 0], a0);
                    a1 = ffma2(hrep[k + 1], wch[k + 1], a1);
                    a2 = ffma2(hrep[k + 2], wch[k + 2], a2);
                    a3 = ffma2(hrep[k + 3], wch[k + 3], a3);
                }
                a0 = fadd2(a0, a1);
                a2 = fadd2(a2, a3);
                a0 = fadd2(a0, a2);
                float lo, hi; unpack2(a0, lo, hi);
                pre = lo + hi;
            }
            const float h = (pre > 0.f) ? pre : (__expf(pre) - 1.f); // ELU
            hslot[hb][lane] = h;
            __syncwarp();
            {
                const ulonglong2* hp = reinterpret_cast<const ulonglong2*>(hslot[hb]);
                #pragma unroll
                for (int k = 0; k < 8; k++) {
                    ulonglong2 v = hp[k];
                    hrep[2 * k] = v.x; hrep[2 * k + 1] = v.y;
                }
            }
            hb ^= 1;
            return h;
        };

        // Head: logP contribution for column cc (off the recurrence path).
        auto head = [&](float h, int xc) {
            float q = h * dwo;
            #pragma unroll
            for (int off = 16; off; off >>= 1)
                q += __shfl_xor_sync(FULLMASK, q, off);
            q += dbo;
            const float t = (xc == 1) ? q : -q;
            logacc -= fmaxf(t, 0.f) + __logf(1.f + __expf(-fabsf(t)));
        };

        // Produce next row's vertical pre-activation pair for column cc,
        // using the freshly replicated h (= cV for row r+1 at cc).
        auto produce = [&](int cc, float wa, float wb) {
            unsigned long long v0 = pack2(bv + wa + wb, 0.f);
            unsigned long long v1 = 0ull;
            #pragma unroll
            for (int k = 0; k < 16; k += 2) {
                v0 = ffma2(hrep[k + 0], wcv[k + 0], v0);
                v1 = ffma2(hrep[k + 1], wcv[k + 1], v1);
            }
            vbuf[(cc << 5) + lane] = fadd2(v0, v1);
        };

        // j = 0 (row-start column: no horizontal carry)
        {
            const float h = stepbody(c, true);
            const int xc = xrow[cur][c];
            head(h, xc);
            if (notlast) {
                const int xn = xrow[nxt][c + dir];   // scan-predecessor in row r+1
                produce(c, xn ? win1 : win0, xc ? win3 : win2);
            }
            c += dir;
        }
        // j = 1 .. L-2
        #pragma unroll 2
        for (int j = 1; j < L - 1; j++) {
            const float h = stepbody(c, false);
            const int xc = xrow[cur][c];
            head(h, xc);
            if (notlast) {
                const int xn = xrow[nxt][c + dir];
                produce(c, xn ? win1 : win0, xc ? win3 : win2);
            }
            c += dir;
        }
        // j = L-1 (last scanned column: row r+1 starts here -> no stateH term)
        {
            const float h = stepbody(c, false);
            const int xc = xrow[cur][c];
            head(h, xc);
            if (notlast) {
                produce(c, 0.f, xc ? win3 : win2);
            }
        }
    }

    if (lane == 0) out[sample] = 0.5f * logacc;
}

extern "C" void kernel_launch(void* const* d_in, const int* in_sizes, int n_in,
                              void* d_out, int out_size)
{
    const int*   x    = (const int*)  d_in[0];
    const float* Win  = (const float*)d_in[1];
    const float* WcH  = (const float*)d_in[2];
    const float* WcV  = (const float*)d_in[3];
    const float* bV   = (const float*)d_in[4];
    const float* Wout = (const float*)d_in[5];
    const float* bout = (const float*)d_in[6];
    float* out = (float*)d_out;

    rnn2d_kernel<<<B, 32>>>(x, Win, WcH, WcV, bV, Wout, bout, out);
}

// round 3
// speedup vs baseline: 2.2563x; 2.2563x over previous
#include <cuda_runtime.h>
#include <cstdint>

#define FULLMASK 0xFFFFFFFFu

static constexpr int L = 64;
static constexpr int H = 32;
static constexpr int B = 1024;

__device__ __forceinline__ unsigned long long pack2(float lo, float hi) {
    unsigned long long r;
    asm("mov.b64 %0, {%1, %2};" : "=l"(r) : "f"(lo), "f"(hi));
    return r;
}
__device__ __forceinline__ void unpack2(unsigned long long v, float& lo, float& hi) {
    asm("mov.b64 {%0, %1}, %2;" : "=f"(lo), "=f"(hi) : "l"(v));
}
__device__ __forceinline__ unsigned long long ffma2(unsigned long long a,
                                                    unsigned long long b,
                                                    unsigned long long c) {
    unsigned long long d;
    asm("fma.rn.f32x2 %0, %1, %2, %3;" : "=l"(d) : "l"(a), "l"(b), "l"(c));
    return d;
}
__device__ __forceinline__ unsigned long long fadd2(unsigned long long a,
                                                    unsigned long long b) {
    unsigned long long d;
    asm("add.rn.f32x2 %0, %1, %2;" : "=l"(d) : "l"(a), "l"(b));
    return d;
}

__global__ void __launch_bounds__(32)
rnn2d_kernel(const int* __restrict__ x,        // [B, L, L] in {0,1}
             const float* __restrict__ Win,    // [4, H]
             const float* __restrict__ WcH,    // [H, H]
             const float* __restrict__ WcV,    // [H, H]
             const float* __restrict__ bV,     // [H]
             const float* __restrict__ Wout,   // [H, 2]
             const float* __restrict__ bout,   // [2]
             float* __restrict__ out)          // [B]
{
    __shared__ __align__(16) float hrow[L * H];  // [c][lane]: h of current row
    __shared__ __align__(16) float vbuf[L * H];  // [c][lane]: vertical pre-act (scalar)
    __shared__ int xrow[2][L];

    const int lane = threadIdx.x;
    const int sample = blockIdx.x;

    // ---- per-lane weights ----
    const float win0 = Win[0 * H + lane];
    const float win1 = Win[1 * H + lane];
    const float win2 = Win[2 * H + lane];
    const float win3 = Win[3 * H + lane];
    const float bv   = bV[lane];
    const float dbo  = bout[0] - bout[1];

    unsigned long long wch[16], wcv[16], dw2[16];
    #pragma unroll
    for (int k = 0; k < 16; k++) {
        wch[k] = pack2(WcH[(2 * k) * H + lane], WcH[(2 * k + 1) * H + lane]);
        wcv[k] = pack2(WcV[(2 * k) * H + lane], WcV[(2 * k + 1) * H + lane]);
        dw2[k] = pack2(Wout[(2 * k) * 2 + 0] - Wout[(2 * k) * 2 + 1],
                       Wout[(2 * k + 1) * 2 + 0] - Wout[(2 * k + 1) * 2 + 1]);
    }

    const int* xs = x + (long)sample * (L * L);

    // Row 0 preamble: x row 0, and vbuf for row 0 (cV = 0, stateV = 0).
    xrow[0][lane]      = xs[lane];
    xrow[0][lane + 32] = xs[lane + 32];
    __syncwarp();
    #pragma unroll 4
    for (int c2 = 0; c2 < L; c2++) {
        const float wa = (c2 == 0) ? 0.f : (xrow[0][c2 - 1] ? win1 : win0);
        vbuf[(c2 << 5) + lane] = bv + wa;
    }

    unsigned long long hrep[16];
    float logacc = 0.f;

    for (int r = 0; r < L; r++) {
        const int cur = r & 1, nxt = cur ^ 1;
        const bool notlast = (r < L - 1);

        if (notlast) {
            xrow[nxt][lane]      = xs[(r + 1) * L + lane];
            xrow[nxt][lane + 32] = xs[(r + 1) * L + lane + 32];
        }
        // Orders: xrow[nxt] writes; prev row's head reads of hrow vs. this
        // row's first hrow store.
        __syncwarp();

        const int dir = (r & 1) ? -1 : 1;
        int c = (r & 1) ? (L - 1) : 0;
        float vpre = vbuf[(c << 5) + lane];

        // ---- one column step (first: no horizontal carry; last: no advance) ----
        auto step = [&](int j, bool first, bool last) {
            float pre;
            if (first) {
                pre = vpre;
            } else {
                unsigned long long a0 = pack2(vpre, 0.f), a1 = 0ull, a2 = 0ull, a3 = 0ull;
                #pragma unroll
                for (int k = 0; k < 16; k += 4) {
                    a0 = ffma2(hrep[k + 0], wch[k + 0], a0);
                    a1 = ffma2(hrep[k + 1], wch[k + 1], a1);
                    a2 = ffma2(hrep[k + 2], wch[k + 2], a2);
                    a3 = ffma2(hrep[k + 3], wch[k + 3], a3);
                }
                a0 = fadd2(a0, a1);
                a2 = fadd2(a2, a3);
                a0 = fadd2(a0, a2);
                float lo, hi; unpack2(a0, lo, hi);
                pre = lo + hi;
            }
            const float h = (pre > 0.f) ? pre : (__expf(pre) - 1.f); // ELU
            hrow[(c << 5) + lane] = h;
            __syncwarp();
            const int cn = c + dir;
            if (!last) vpre = vbuf[(cn << 5) + lane];   // prefetch next column
            // Broadcast-replicate h (same address all lanes -> conflict-free).
            {
                const ulonglong2* hp = reinterpret_cast<const ulonglong2*>(hrow + (c << 5));
                #pragma unroll
                for (int k = 0; k < 8; k++) {
                    ulonglong2 v = hp[k];
                    hrep[2 * k] = v.x; hrep[2 * k + 1] = v.y;
                }
            }
            // Produce next row's vertical pre-activation at this column.
            if (notlast) {
                const int xc = xrow[cur][c];
                const float wa = last ? 0.f : (xrow[nxt][cn] ? win1 : win0);
                const float wb = xc ? win3 : win2;
                unsigned long long v0 = pack2(bv + wa + wb, 0.f), v1 = 0ull;
                #pragma unroll
                for (int k = 0; k < 16; k += 2) {
                    v0 = ffma2(hrep[k + 0], wcv[k + 0], v0);
                    v1 = ffma2(hrep[k + 1], wcv[k + 1], v1);
                }
                v0 = fadd2(v0, v1);
                float lo, hi; unpack2(v0, lo, hi);
                vbuf[(c << 5) + lane] = lo + hi;
            }
            if (!last) c = cn;
        };

        step(0, true, false);
        #pragma unroll 2
        for (int j = 1; j < L - 1; j++) step(j, false, false);
        step(L - 1, false, true);

        // ---- row-batched output head: lane handles columns lane, lane+32 ----
        #pragma unroll
        for (int t = 0; t < 2; t++) {
            const int cc = lane + 32 * t;
            const ulonglong2* hcol = reinterpret_cast<const ulonglong2*>(hrow + (cc << 5));
            unsigned long long q0 = 0ull, q1 = 0ull;
            #pragma unroll
            for (int k = 0; k < 8; k++) {
                const int kk = (k + lane) & 7;   // bank-rotate: 4-way max conflict
                ulonglong2 hv = hcol[kk];
                q0 = ffma2(hv.x, dw2[2 * kk + 0], q0);
                q1 = ffma2(hv.y, dw2[2 * kk + 1], q1);
            }
            q0 = fadd2(q0, q1);
            float lo, hi; unpack2(q0, lo, hi);
            const float q = lo + hi + dbo;
            const int xc = xrow[cur][cc];
            const float tt = (xc == 1) ? q : -q;
            logacc -= fmaxf(tt, 0.f) + __logf(1.f + __expf(-fabsf(tt)));
        }
    }

    // Final cross-lane reduction of per-lane log-prob partials (once per kernel).
    #pragma unroll
    for (int off = 16; off; off >>= 1)
        logacc += __shfl_xor_sync(FULLMASK, logacc, off);
    if (lane == 0) out[sample] = 0.5f * logacc;
}

extern "C" void kernel_launch(void* const* d_in, const int* in_sizes, int n_in,
                              void* d_out, int out_size)
{
    const int*   x    = (const int*)  d_in[0];
    const float* Win  = (const float*)d_in[1];
    const float* WcH  = (const float*)d_in[2];
    const float* WcV  = (const float*)d_in[3];
    const float* bV   = (const float*)d_in[4];
    const float* Wout = (const float*)d_in[5];
    const float* bout = (const float*)d_in[6];
    float* out = (float*)d_out;

    rnn2d_kernel<<<B, 32>>>(x, Win, WcH, WcV, bV, Wout, bout, out);
}

// round 4
// speedup vs baseline: 2.5900x; 1.1479x over previous
#include <cuda_runtime.h>
#include <cstdint>

#define FULLMASK 0xFFFFFFFFu

static constexpr int L = 64;
static constexpr int H = 32;
static constexpr int B = 1024;

__device__ __forceinline__ unsigned long long pack2(float lo, float hi) {
    unsigned long long r;
    asm("mov.b64 %0, {%1, %2};" : "=l"(r) : "f"(lo), "f"(hi));
    return r;
}
__device__ __forceinline__ void unpack2(unsigned long long v, float& lo, float& hi) {
    asm("mov.b64 {%0, %1}, %2;" : "=f"(lo), "=f"(hi) : "l"(v));
}
__device__ __forceinline__ unsigned long long ffma2(unsigned long long a,
                                                    unsigned long long b,
                                                    unsigned long long c) {
    unsigned long long d;
    asm("fma.rn.f32x2 %0, %1, %2, %3;" : "=l"(d) : "l"(a), "l"(b), "l"(c));
    return d;
}
__device__ __forceinline__ unsigned long long fadd2(unsigned long long a,
                                                    unsigned long long b) {
    unsigned long long d;
    asm("add.rn.f32x2 %0, %1, %2;" : "=l"(d) : "l"(a), "l"(b));
    return d;
}
__device__ __forceinline__ float elu1(float pre) {
    // exact branchless ELU(alpha=1): pre>0 -> pre ; pre<=0 -> exp(pre)-1
    return fmaxf(pre, 0.f) + (__expf(fminf(pre, 0.f)) - 1.f);
}

__global__ void __launch_bounds__(32)
rnn2d_kernel(const int* __restrict__ x,        // [B, L, L] in {0,1}
             const float* __restrict__ Win,    // [4, H]
             const float* __restrict__ WcH,    // [H, H]
             const float* __restrict__ WcV,    // [H, H]
             const float* __restrict__ bV,     // [H]
             const float* __restrict__ Wout,   // [H, 2]
             const float* __restrict__ bout,   // [2]
             float* __restrict__ out)          // [B]
{
    __shared__ __align__(16) float hrow[L * H];  // [c][lane]: h of current row
    __shared__ __align__(16) float vbuf[L * H];  // [c][lane]: vertical pre-act (scalar)
    __shared__ int xrow[2][L];
    __shared__ __align__(16) float dws[H];       // Wout[:,0]-Wout[:,1]

    const int lane = threadIdx.x;
    const int sample = blockIdx.x;

    // ---- per-lane weights ----
    const float win0 = Win[0 * H + lane];
    const float win1 = Win[1 * H + lane];
    const float win2 = Win[2 * H + lane];
    const float win3 = Win[3 * H + lane];
    const float bv   = bV[lane];
    const float dbo  = bout[0] - bout[1];
    dws[lane] = Wout[lane * 2 + 0] - Wout[lane * 2 + 1];

    unsigned long long wch[16], wcv[16];
    #pragma unroll
    for (int k = 0; k < 16; k++) {
        wch[k] = pack2(WcH[(2 * k) * H + lane], WcH[(2 * k + 1) * H + lane]);
        wcv[k] = pack2(WcV[(2 * k) * H + lane], WcV[(2 * k + 1) * H + lane]);
    }

    const int* xs = x + (long)sample * (L * L);

    // Row 0 x, and vbuf for row 0 (cV = 0, stateV = 0 -> bias + stateH only).
    xrow[0][lane]      = xs[lane];
    xrow[0][lane + 32] = xs[lane + 32];
    __syncwarp();
    {
        float wa = 0.f;
        #pragma unroll 4
        for (int c = 0; c < L; c++) {
            vbuf[(c << 5) + lane] = bv + wa;
            wa = xrow[0][c] ? win1 : win0;
        }
    }

    unsigned long long hrep[16];
    float logacc = 0.f;
    int c0 = 0, dir = 1;

    for (int r = 0; r < L; r++) {
        const int cur = r & 1, nxt = cur ^ 1;

        // Order prev row's cross-lane hrow/xrow reads before this row's writes.
        __syncwarp();
        const int rl = (r < L - 1) ? r + 1 : r;      // clamp (last row: harmless)
        xrow[nxt][lane]      = xs[rl * L + lane];
        xrow[nxt][lane + 32] = xs[rl * L + lane + 32];
        __syncwarp();

        int c = c0;

        // ---- step 0: no horizontal carry ----
        {
            const float pre = vbuf[(c << 5) + lane];
            const float h = elu1(pre);
            hrow[(c << 5) + lane] = h;
            __syncwarp();
            const ulonglong2* hp = reinterpret_cast<const ulonglong2*>(hrow + (c << 5));
            #pragma unroll
            for (int k = 0; k < 8; k++) {
                ulonglong2 v = hp[k];
                hrep[2 * k] = v.x; hrep[2 * k + 1] = v.y;
            }
        }
        float vpre   = vbuf[((c + dir) << 5) + lane];
        int   xc_cur = xrow[cur][c];
        int   xn_next = xrow[nxt][c + dir];

        // ---- fused loop: with hrep(c), compute pre(c+dir) AND produce(c) ----
        #pragma unroll 2
        for (int j = 0; j < L - 1; j++) {
            const int cn = c + dir;
            const float rsum = bv + (xn_next ? win1 : win0) + (xc_cur ? win3 : win2);

            unsigned long long a0 = pack2(vpre, 0.f), a1 = 0ull, a2 = 0ull, a3 = 0ull;
            unsigned long long v0 = pack2(rsum, 0.f), v1 = 0ull, v2 = 0ull, v3 = 0ull;
            #pragma unroll
            for (int k = 0; k < 16; k += 4) {
                a0 = ffma2(hrep[k + 0], wch[k + 0], a0);
                a1 = ffma2(hrep[k + 1], wch[k + 1], a1);
                a2 = ffma2(hrep[k + 2], wch[k + 2], a2);
                a3 = ffma2(hrep[k + 3], wch[k + 3], a3);
            }
            #pragma unroll
            for (int k = 0; k < 16; k += 4) {
                v0 = ffma2(hrep[k + 0], wcv[k + 0], v0);
                v1 = ffma2(hrep[k + 1], wcv[k + 1], v1);
                v2 = ffma2(hrep[k + 2], wcv[k + 2], v2);
                v3 = ffma2(hrep[k + 3], wcv[k + 3], v3);
            }
            a0 = fadd2(a0, a1);
            a2 = fadd2(a2, a3);
            a0 = fadd2(a0, a2);
            float lo, hi; unpack2(a0, lo, hi);
            const float pre = lo + hi;
            const float h = elu1(pre);
            hrow[(cn << 5) + lane] = h;
            __syncwarp();

            // Broadcast-replicate h(cn); fill the stall window with the v-tail
            // and next-iter prefetches.
            {
                const ulonglong2* hp = reinterpret_cast<const ulonglong2*>(hrow + (cn << 5));
                #pragma unroll
                for (int k = 0; k < 8; k++) {
                    ulonglong2 v = hp[k];
                    hrep[2 * k] = v.x; hrep[2 * k + 1] = v.y;
                }
            }
            int cn2 = cn + dir;
            cn2 = (cn2 < 0) ? 0 : ((cn2 > L - 1) ? L - 1 : cn2);   // clamp; stale ok
            vpre = vbuf[(cn2 << 5) + lane];
            const int xc2 = xrow[cur][cn];
            const int xn2 = xrow[nxt][cn2];

            v0 = fadd2(v0, v1);
            v2 = fadd2(v2, v3);
            v0 = fadd2(v0, v2);
            float vl, vh; unpack2(v0, vl, vh);
            vbuf[(c << 5) + lane] = vl + vh;   // produce(c): own-lane slot, no sync

            xc_cur = xc2; xn_next = xn2;
            c = cn;
        }

        // ---- epilogue: produce(c_last) — next row starts here, no stateH ----
        {
            unsigned long long v0 = pack2(bv + (xc_cur ? win3 : win2), 0.f);
            unsigned long long v1 = 0ull, v2 = 0ull, v3 = 0ull;
            #pragma unroll
            for (int k = 0; k < 16; k += 4) {
                v0 = ffma2(hrep[k + 0], wcv[k + 0], v0);
                v1 = ffma2(hrep[k + 1], wcv[k + 1], v1);
                v2 = ffma2(hrep[k + 2], wcv[k + 2], v2);
                v3 = ffma2(hrep[k + 3], wcv[k + 3], v3);
            }
            v0 = fadd2(v0, v1);
            v2 = fadd2(v2, v3);
            v0 = fadd2(v0, v2);
            float vl, vh; unpack2(v0, vl, vh);
            vbuf[(c << 5) + lane] = vl + vh;
        }

        // ---- row-batched output head: lane handles columns lane, lane+32 ----
        #pragma unroll
        for (int t = 0; t < 2; t++) {
            const int cc = lane + 32 * t;
            const ulonglong2* hcol = reinterpret_cast<const ulonglong2*>(hrow + (cc << 5));
            const ulonglong2* dwp  = reinterpret_cast<const ulonglong2*>(dws);
            unsigned long long q0 = 0ull, q1 = 0ull;
            #pragma unroll
            for (int k = 0; k < 8; k++) {
                const int kk = (k + lane) & 7;   // bank-rotate
                ulonglong2 hv = hcol[kk];
                ulonglong2 dv = dwp[kk];
                q0 = ffma2(hv.x, dv.x, q0);
                q1 = ffma2(hv.y, dv.y, q1);
            }
            q0 = fadd2(q0, q1);
            float lo, hi; unpack2(q0, lo, hi);
            const float q = lo + hi + dbo;
            const int xc = xrow[cur][cc];
            const float tt = xc ? q : -q;
            logacc -= fmaxf(tt, 0.f) + __logf(1.f + __expf(-fabsf(tt)));
        }

        c0 = c;          // snake: next row starts where this one ended
        dir = -dir;
    }

    #pragma unroll
    for (int off = 16; off; off >>= 1)
        logacc += __shfl_xor_sync(FULLMASK, logacc, off);
    if (lane == 0) out[sample] = 0.5f * logacc;
}

extern "C" void kernel_launch(void* const* d_in, const int* in_sizes, int n_in,
                              void* d_out, int out_size)
{
    const int*   x    = (const int*)  d_in[0];
    const float* Win  = (const float*)d_in[1];
    const float* WcH  = (const float*)d_in[2];
    const float* WcV  = (const float*)d_in[3];
    const float* bV   = (const float*)d_in[4];
    const float* Wout = (const float*)d_in[5];
    const float* bout = (const float*)d_in[6];
    float* out = (float*)d_out;

    rnn2d_kernel<<<B, 32>>>(x, Win, WcH, WcV, bV, Wout, bout, out);
}